// round 4
// baseline (speedup 1.0000x reference)
#include <cuda_runtime.h>
#include <math.h>

// Problem constants (from reference)
#define N_NODES 50000
#define N_EDGES 800000
#define CIN     128
#define CH      64
#define NG      256
#define NHID    8                      // hidden GCN layers after layer0
#define ETOT    (N_EDGES + N_NODES)    // edges + self loops = 850000

#define SCAN_B   1024
#define SCAN_NB  ((N_NODES + SCAN_B - 1) / SCAN_B)   // 49

// ---------------- scratch (static __device__; no allocation) ----------------
__device__ float g_h  [N_NODES * CH];   // aggregated features
__device__ float g_msg[N_NODES * CH];   // dis-scaled GEMM output (messages)
__device__ float g_hn [N_NODES * CH];   // node-transform output
__device__ float g_dis[N_NODES];
__device__ int   g_counts[N_NODES];
__device__ int   g_rowptr[N_NODES + 1];
__device__ int   g_fill  [N_NODES];
__device__ int   g_col   [ETOT];
__device__ float g_pool[NG * CH];
__device__ float g_pt  [NG * CH];
__device__ int   g_part[SCAN_NB];

// ---------------- setup kernels ----------------
__global__ void k_init()
{
    int i = blockIdx.x * blockDim.x + threadIdx.x;
    if (i < N_NODES) g_counts[i] = 1;              // self loop
    if (i < NG * CH) g_pool[i] = 0.0f;
}

__global__ void k_degree(const int* __restrict__ dst)
{
    int e = blockIdx.x * blockDim.x + threadIdx.x;
    if (e < N_EDGES) atomicAdd(&g_counts[dst[e]], 1);
}

// per-block exclusive scan of g_counts -> g_rowptr, block totals -> g_part
__global__ void k_scan1()
{
    __shared__ int s[SCAN_B];
    int i = blockIdx.x * SCAN_B + threadIdx.x;
    int v = (i < N_NODES) ? g_counts[i] : 0;
    s[threadIdx.x] = v;
    __syncthreads();
    #pragma unroll
    for (int off = 1; off < SCAN_B; off <<= 1) {
        int t = 0;
        if (threadIdx.x >= off) t = s[threadIdx.x - off];
        __syncthreads();
        s[threadIdx.x] += t;
        __syncthreads();
    }
    if (i < N_NODES) g_rowptr[i] = s[threadIdx.x] - v;   // exclusive
    if (threadIdx.x == SCAN_B - 1) g_part[blockIdx.x] = s[threadIdx.x];
}

__global__ void k_scan2()
{
    if (threadIdx.x == 0) {
        int run = 0;
        for (int b = 0; b < SCAN_NB; ++b) {
            int t = g_part[b];
            g_part[b] = run;
            run += t;
        }
    }
}

__global__ void k_scan3()
{
    int i = blockIdx.x * blockDim.x + threadIdx.x;
    if (i >= N_NODES) return;
    int rp = g_rowptr[i] + g_part[i / SCAN_B];
    g_rowptr[i] = rp;
    g_dis[i] = rsqrtf((float)g_counts[i]);   // deg >= 1 always (self loop)
    g_col[rp] = i;                           // self loop in slot 0
    g_fill[i] = 1;
    if (i == 0) g_rowptr[N_NODES] = ETOT;
}

__global__ void k_fill(const int* __restrict__ src, const int* __restrict__ dst)
{
    int e = blockIdx.x * blockDim.x + threadIdx.x;
    if (e >= N_EDGES) return;
    int d = dst[e];
    int p = atomicAdd(&g_fill[d], 1);
    g_col[g_rowptr[d] + p] = src[e];
}

// ---------------- SGEMM: C[M,64] = A[M,K] @ B[K,64], optional dis-scale ----
// BM=64 BN=64 BK=32, 256 threads, 4x4 microtile, float4 smem reads.
template<int K, bool SCALE>
__global__ void sgemm64(const float* __restrict__ A, const float* __restrict__ B,
                        float* __restrict__ C, int M)
{
    __shared__ float As[32][64];   // As[k][row]
    __shared__ float Bs[32][64];   // Bs[k][col]
    int tid  = threadIdx.x;
    int trow = (tid >> 4) * 4;     // 0..60
    int tcol = (tid & 15) * 4;     // 0..60
    int rowBase = blockIdx.x * 64;

    float acc[4][4] = {};

    #pragma unroll
    for (int kk = 0; kk < K; kk += 32) {
        // load A tile 64x32: 512 float4 total, 2 per thread
        #pragma unroll
        for (int l = 0; l < 2; ++l) {
            int lin = tid + l * 256;
            int r   = lin >> 3;            // 0..63
            int k0  = (lin & 7) * 4;       // 0..28
            int gr  = rowBase + r;
            float4 v = make_float4(0.f, 0.f, 0.f, 0.f);
            if (gr < M) v = *(const float4*)&A[(long)gr * K + kk + k0];
            As[k0 + 0][r] = v.x;
            As[k0 + 1][r] = v.y;
            As[k0 + 2][r] = v.z;
            As[k0 + 3][r] = v.w;
        }
        // load B tile 32x64: 512 float4 total, 2 per thread
        #pragma unroll
        for (int l = 0; l < 2; ++l) {
            int lin = tid + l * 256;
            int k   = lin >> 4;            // 0..31
            int c0  = (lin & 15) * 4;      // 0..60
            *(float4*)&Bs[k][c0] = *(const float4*)&B[(kk + k) * 64 + c0];
        }
        __syncthreads();
        #pragma unroll
        for (int k = 0; k < 32; ++k) {
            float4 a = *(const float4*)&As[k][trow];
            float4 b = *(const float4*)&Bs[k][tcol];
            float av[4] = {a.x, a.y, a.z, a.w};
            float bv[4] = {b.x, b.y, b.z, b.w};
            #pragma unroll
            for (int i = 0; i < 4; ++i)
                #pragma unroll
                for (int j = 0; j < 4; ++j)
                    acc[i][j] = fmaf(av[i], bv[j], acc[i][j]);
        }
        __syncthreads();
    }

    #pragma unroll
    for (int i = 0; i < 4; ++i) {
        int gr = rowBase + trow + i;
        if (gr < M) {
            float s = SCALE ? g_dis[gr] : 1.0f;
            float4 o;
            o.x = s * acc[i][0];
            o.y = s * acc[i][1];
            o.z = s * acc[i][2];
            o.w = s * acc[i][3];
            *(float4*)&C[(long)gr * 64 + tcol] = o;
        }
    }
}

// ---------------- aggregation: warp per dst row, float2 per lane ----------
// 4-edge unroll for MLP (L2-latency bound gathers; 12.8 MB working set in L2).
__global__ void k_agg(const float* __restrict__ msg, const float* __restrict__ bias,
                      float* __restrict__ out)
{
    int warp = (blockIdx.x * blockDim.x + threadIdx.x) >> 5;
    int lane = threadIdx.x & 31;
    if (warp >= N_NODES) return;
    int beg = g_rowptr[warp];
    int end = g_rowptr[warp + 1];
    const float2* m2 = (const float2*)msg;
    float ax = 0.f, ay = 0.f;
    float bx = 0.f, by = 0.f;
    float cx = 0.f, cy = 0.f;
    float dx = 0.f, dy = 0.f;
    int p = beg;
    for (; p + 4 <= end; p += 4) {
        int j0 = __ldg(&g_col[p]);
        int j1 = __ldg(&g_col[p + 1]);
        int j2 = __ldg(&g_col[p + 2]);
        int j3 = __ldg(&g_col[p + 3]);
        float2 v0 = __ldg(&m2[j0 * 32 + lane]);
        float2 v1 = __ldg(&m2[j1 * 32 + lane]);
        float2 v2 = __ldg(&m2[j2 * 32 + lane]);
        float2 v3 = __ldg(&m2[j3 * 32 + lane]);
        ax += v0.x; ay += v0.y;
        bx += v1.x; by += v1.y;
        cx += v2.x; cy += v2.y;
        dx += v3.x; dy += v3.y;
    }
    for (; p < end; ++p) {
        int j = __ldg(&g_col[p]);
        float2 v = __ldg(&m2[j * 32 + lane]);
        ax += v.x; ay += v.y;
    }
    ax += bx; ay += by;
    cx += dx; cy += dy;
    ax += cx; ay += cy;
    float s = g_dis[warp];
    float2 o;
    o.x = fmaxf(fmaf(s, ax, bias[2 * lane]),     0.f);
    o.y = fmaxf(fmaf(s, ay, bias[2 * lane + 1]), 0.f);
    ((float2*)out)[warp * 32 + lane] = o;
}

// ---------------- pooling with sorted-batch run aggregation --------------
__global__ void k_pool(const int* __restrict__ nb)
{
    int t = blockIdx.x * blockDim.x + threadIdx.x;
    int c  = t & 31;              // float2 column
    int i0 = (t >> 5) * 8;
    if (i0 >= N_NODES) return;
    const float2* h2 = (const float2*)g_hn;
    int iend = min(i0 + 8, N_NODES);
    int curb = nb[i0];
    float ax = 0.f, ay = 0.f;
    for (int i = i0; i < iend; ++i) {
        int b = nb[i];
        if (b != curb) {
            atomicAdd(&g_pool[curb * 64 + 2 * c],     ax);
            atomicAdd(&g_pool[curb * 64 + 2 * c + 1], ay);
            ax = ay = 0.f;
            curb = b;
        }
        float2 v = h2[i * 32 + c];
        ax += v.x;
        ay += v.y;
    }
    atomicAdd(&g_pool[curb * 64 + 2 * c],     ax);
    atomicAdd(&g_pool[curb * 64 + 2 * c + 1], ay);
}

// ---------------- final head: warp per node ------------------------------
__global__ void k_final(const int* __restrict__ nb, const float* __restrict__ waggr,
                        float* __restrict__ out)
{
    int warp = (blockIdx.x * blockDim.x + threadIdx.x) >> 5;
    int lane = threadIdx.x & 31;
    if (warp >= N_NODES) return;
    const float2* h2 = (const float2*)g_hn;
    const float2* p2 = (const float2*)g_pt;
    const float2* w2 = (const float2*)waggr;
    float2 h = h2[warp * 32 + lane];
    float2 r = p2[nb[warp] * 32 + lane];
    float2 wa = w2[lane];
    float2 wb = w2[32 + lane];
    float z = fmaxf(h.x, 0.f) * wa.x + fmaxf(h.y, 0.f) * wa.y
            + fmaxf(r.x, 0.f) * wb.x + fmaxf(r.y, 0.f) * wb.y;
    #pragma unroll
    for (int off = 16; off > 0; off >>= 1)
        z += __shfl_down_sync(0xffffffffu, z, off);
    if (lane == 0) out[warp] = tanhf(z);
}

// ---------------- launch ---------------------------------------------------
extern "C" void kernel_launch(void* const* d_in, const int* in_sizes, int n_in,
                              void* d_out, int out_size)
{
    const float* x       = (const float*)d_in[0];
    const int*   ei      = (const int*)  d_in[1];
    const int*   nb      = (const int*)  d_in[2];
    const float* w0      = (const float*)d_in[3];
    const float* b0      = (const float*)d_in[4];
    const float* w_hid   = (const float*)d_in[5];
    const float* b_hid   = (const float*)d_in[6];
    const float* w_node  = (const float*)d_in[7];
    const float* w_grph  = (const float*)d_in[8];
    const float* w_aggr  = (const float*)d_in[9];
    float*       out     = (float*)d_out;

    const int* src = ei;
    const int* dst = ei + N_EDGES;

    float *p_h, *p_msg, *p_hn, *p_pool, *p_pt;
    cudaGetSymbolAddress((void**)&p_h,    g_h);
    cudaGetSymbolAddress((void**)&p_msg,  g_msg);
    cudaGetSymbolAddress((void**)&p_hn,   g_hn);
    cudaGetSymbolAddress((void**)&p_pool, g_pool);
    cudaGetSymbolAddress((void**)&p_pt,   g_pt);

    const int T = 256;
    int gridN  = (N_NODES + T - 1) / T;          // 196
    int gridE  = (N_EDGES + T - 1) / T;          // 3125
    int gridW  = (N_NODES * 32 + T - 1) / T;     // warp-per-node kernels: 6250
    int gridM  = (N_NODES + 63) / 64;            // GEMM blocks: 782
    int gridP  = (((N_NODES + 7) / 8) * 32 + T - 1) / T;

    // --- graph structure (rebuilt every launch; edges are an input) ---
    k_init  <<<gridN, T>>>();
    k_degree<<<gridE, T>>>(dst);
    k_scan1 <<<SCAN_NB, SCAN_B>>>();
    k_scan2 <<<1, 32>>>();
    k_scan3 <<<gridN, T>>>();
    k_fill  <<<gridE, T>>>(src, dst);

    // --- layer 0: K = CIN = 128 ---
    sgemm64<CIN, true><<<gridM, T>>>(x, w0, p_msg, N_NODES);
    k_agg<<<gridW, T>>>(p_msg, b0, p_h);

    // --- hidden layers: K = 64 ---
    for (int l = 0; l < NHID; ++l) {
        sgemm64<CH, true><<<gridM, T>>>(p_h, w_hid + l * CH * CH, p_msg, N_NODES);
        k_agg<<<gridW, T>>>(p_msg, b_hid + l * CH, p_h);
    }

    // --- node transform (no scale / bias / relu) ---
    sgemm64<CH, false><<<gridM, T>>>(p_h, w_node, p_hn, N_NODES);

    // --- pool + graph transform ---
    k_pool<<<gridP, T>>>(nb);
    sgemm64<CH, false><<<(NG + 63) / 64, T>>>(p_pool, w_grph, p_pt, NG);

    // --- head ---
    k_final<<<gridW, T>>>(nb, w_aggr, out);
}